// round 15
// baseline (speedup 1.0000x reference)
#include <cuda_runtime.h>
#include <cuda_fp16.h>
#include <cstdint>

#define NU 50000
#define NI 50000
#define NN 100000            // NU + NI
#define DD 64
#define EE 1600000
#define NB 4096              // batch pairs
#define CAP 96               // padded adjacency capacity (deg ~ Poisson(32))
#define FULLM 0xffffffffu

// ---------------- device scratch (static, no runtime allocation) -----------
__device__ int            g_deg[NN];
__device__ float          g_dinv[NN];
__device__ unsigned short g_ku[EE];   // occurrence index of edge within user row
__device__ unsigned short g_ki[EE];   // occurrence index of edge within item row
__device__ int            g_col[(size_t)NN * CAP];   // padded adjacency
__device__ unsigned char  g_flag[NN]; // 1 if node appears in users/items sample
// ping-pong fp16 gather buffers holding xs = dinv * x  (row = 128B)
__device__ __half2 g_x[(size_t)NN * 32];
__device__ __half2 g_y[(size_t)NN * 32];
__device__ float   g_acc[(size_t)NN * DD];  // fp32 sum, maintained ONLY at flagged nodes

#define CNT_BLKS ((EE + 255) / 256)          // 6250
#define FLG_BLKS ((2 * NB + 255) / 256)      // 32
#define FIL_BLKS ((EE + 255) / 256)          // 6250
#define INI_BLKS ((NN * 32 + 255) / 256)     // 12500

// ---------------- graph build ----------------------------------------------

// count degrees + record occurrence indices; tail blocks mark sampled nodes
__global__ void k_count(const int* __restrict__ edge,
                        const int* __restrict__ users,
                        const int* __restrict__ items) {
    int b = blockIdx.x;
    if (b < CNT_BLKS) {
        int e = b * 256 + threadIdx.x;
        if (e >= EE) return;
        int u  = edge[e];
        int it = NU + edge[EE + e];
        g_ku[e] = (unsigned short)atomicAdd(&g_deg[u],  1);
        g_ki[e] = (unsigned short)atomicAdd(&g_deg[it], 1);
    } else {
        int i = (b - CNT_BLKS) * 256 + threadIdx.x;
        if (i < NB)           g_flag[users[i]] = 1;
        else if (i < 2 * NB)  g_flag[NU + items[i - NB]] = 1;
    }
}

// dinv from final degrees
__global__ void k_dinv() {
    int i = blockIdx.x * blockDim.x + threadIdx.x;
    if (i >= NN) return;
    int d = g_deg[i];
    g_dinv[i] = (d > 0) ? rsqrtf((float)d) : 0.0f;
}

// fused: blocks [0, FIL_BLKS) fill the padded adjacency (atomic-free);
// blocks [FIL_BLKS, ...) do initx (x = fp16(dinv*e0); acc = e0 at flagged)
__global__ void k_fillinit(const int* __restrict__ edge,
                           const float* __restrict__ ue,
                           const float* __restrict__ ie) {
    int b = blockIdx.x;
    if (b < FIL_BLKS) {
        int e = b * 256 + threadIdx.x;
        if (e >= EE) return;
        int u  = edge[e];
        int it = NU + edge[EE + e];
        g_col[(size_t)u  * CAP + (int)g_ku[e]] = it;
        g_col[(size_t)it * CAP + (int)g_ki[e]] = u;
    } else {
        int i = (b - FIL_BLKS) * 256 + threadIdx.x;   // i in [0, NN*32)
        if (i >= NN * 32) return;
        int node = i >> 5;
        int lane = i & 31;
        const float* src = (node < NU) ? (ue + ((size_t)node << 6))
                                       : (ie + ((size_t)(node - NU) << 6));
        float2 v = *((const float2*)src + lane);
        if (g_flag[node])
            *((float2*)(g_acc + ((size_t)node << 6)) + lane) = v;
        float d = g_dinv[node];
        g_x[((size_t)node << 5) + lane] = __floats2half2_rn(d * v.x, d * v.y);
    }
}

// ---------------- propagation ----------------------------------------------

// warp per node, 2 edges per LDG: each half-warp (16 lanes x uint2 = 128B row)
// gathers a different neighbor per load. Col indices fetched 8-wide and
// distributed via shfl.idx. fp16 4-edge trees -> fp32 accum. Halves merged
// via shfl_xor(16). Epilogue: half 1 stores fp16 dst; half 0 updates fp32
// acc only at flagged nodes. Padded CSR: row base = node*CAP, len = deg.
__global__ void k_prop(int flip) {
    const uint2* __restrict__ src = (const uint2*)(flip ? g_y : g_x);
    uint2*       __restrict__ dst = (uint2*)(flip ? g_x : g_y);
    int node = (blockIdx.x * blockDim.x + threadIdx.x) >> 5;
    if (node >= NN) return;
    int lane = threadIdx.x & 31;
    int half = lane >> 4;      // which edge of the pair this lane handles
    int fpos = lane & 15;      // uint2 position within the 128B row
    int beg = node * CAP;
    int end = beg + g_deg[node];
    float s0 = 0.f, s1 = 0.f, s2 = 0.f, s3 = 0.f;
    int j = beg;
    for (; j + 8 <= end; j += 8) {
        int c8 = g_col[j + (lane & 7)];          // lanes 0-7 carry cols j..j+7
        int ca = __shfl_sync(FULLM, c8, half);
        int cb = __shfl_sync(FULLM, c8, 2 + half);
        int cc = __shfl_sync(FULLM, c8, 4 + half);
        int cd = __shfl_sync(FULLM, c8, 6 + half);
        uint2 va = src[((size_t)ca << 4) + fpos];
        uint2 vb = src[((size_t)cb << 4) + fpos];
        uint2 vc = src[((size_t)cc << 4) + fpos];
        uint2 vd = src[((size_t)cd << 4) + fpos];
        __half2 ta = __hadd2(__hadd2(*(__half2*)&va.x, *(__half2*)&vb.x),
                             __hadd2(*(__half2*)&vc.x, *(__half2*)&vd.x));
        __half2 tb = __hadd2(__hadd2(*(__half2*)&va.y, *(__half2*)&vb.y),
                             __hadd2(*(__half2*)&vc.y, *(__half2*)&vd.y));
        float2 fa = __half22float2(ta);
        float2 fb = __half22float2(tb);
        s0 += fa.x; s1 += fa.y; s2 += fb.x; s3 += fb.y;
    }
    for (; j + 2 <= end; j += 2) {               // 2-edge tail steps
        int c = g_col[j + half];
        uint2 v = src[((size_t)c << 4) + fpos];
        float2 fa = __half22float2(*(__half2*)&v.x);
        float2 fb = __half22float2(*(__half2*)&v.y);
        s0 += fa.x; s1 += fa.y; s2 += fb.x; s3 += fb.y;
    }
    if (j < end && half == 0) {                  // odd last edge: half 0 only
        int c = g_col[j];
        uint2 v = src[((size_t)c << 4) + fpos];
        float2 fa = __half22float2(*(__half2*)&v.x);
        float2 fb = __half22float2(*(__half2*)&v.y);
        s0 += fa.x; s1 += fa.y; s2 += fb.x; s3 += fb.y;
    }
    // merge the two half-warps' partial sums (both halves end with full sums)
    s0 += __shfl_xor_sync(FULLM, s0, 16);
    s1 += __shfl_xor_sync(FULLM, s1, 16);
    s2 += __shfl_xor_sync(FULLM, s2, 16);
    s3 += __shfl_xor_sync(FULLM, s3, 16);
    float d = g_dinv[node];
    if (half == 0) {
        if (g_flag[node]) {                      // warp-uniform branch
            float4* ap = (float4*)g_acc + ((size_t)node << 4) + fpos;
            float4 a = *ap;
            a.x += d * s0; a.y += d * s1; a.z += d * s2; a.w += d * s3;
            *ap = a;
        }
    } else {
        float dd = d * d;
        __half2 w0 = __floats2half2_rn(dd * s0, dd * s1);
        __half2 w1 = __floats2half2_rn(dd * s2, dd * s3);
        uint2 w;
        w.x = *(unsigned*)&w0;
        w.y = *(unsigned*)&w1;
        dst[((size_t)node << 4) + fpos] = w;
    }
}

// warp per (user,item) pair: out = dot(acc_u, acc_i) / 25
__global__ void k_dot(const int* __restrict__ users, const int* __restrict__ items,
                      float* __restrict__ out) {
    int w = (blockIdx.x * blockDim.x + threadIdx.x) >> 5;
    if (w >= NB) return;
    int lane = threadIdx.x & 31;
    int u  = users[w];
    int it = NU + items[w];
    float2 a = *((const float2*)(g_acc + ((size_t)u  << 6)) + lane);
    float2 b = *((const float2*)(g_acc + ((size_t)it << 6)) + lane);
    float s = a.x * b.x + a.y * b.y;
    #pragma unroll
    for (int o = 16; o; o >>= 1) s += __shfl_down_sync(FULLM, s, o);
    if (lane == 0) out[w] = s * 0.04f;   // (1/5)*(1/5) from the two means
}

// ---------------- host launcher --------------------------------------------

extern "C" void kernel_launch(void* const* d_in, const int* in_sizes, int n_in,
                              void* d_out, int out_size) {
    const float* uemb  = (const float*)d_in[0];
    const float* iemb  = (const float*)d_in[1];
    const int*   edge  = (const int*)d_in[2];
    const int*   users = (const int*)d_in[3];
    const int*   items = (const int*)d_in[4];
    float*       out   = (float*)d_out;

    const int T = 256;
    void* p = nullptr;
    cudaGetSymbolAddress(&p, g_deg);
    cudaMemsetAsync(p, 0, NN * sizeof(int));
    cudaGetSymbolAddress(&p, g_flag);
    cudaMemsetAsync(p, 0, NN);

    k_count   <<<CNT_BLKS + FLG_BLKS, T>>>(edge, users, items);
    k_dinv    <<<(NN + T - 1) / T, T>>>();
    k_fillinit<<<FIL_BLKS + INI_BLKS, T>>>(edge, uemb, iemb);

    // 4 propagation layers, ping-pong g_x <-> g_y (selected in-kernel)
    k_prop<<<(NN * 32 + T - 1) / T, T>>>(0);
    k_prop<<<(NN * 32 + T - 1) / T, T>>>(1);
    k_prop<<<(NN * 32 + T - 1) / T, T>>>(0);
    k_prop<<<(NN * 32 + T - 1) / T, T>>>(1);

    k_dot<<<(NB * 32 + T - 1) / T, T>>>(users, items, out);
}

// round 16
// speedup vs baseline: 1.0960x; 1.0960x over previous
#include <cuda_runtime.h>
#include <cuda_fp16.h>
#include <cstdint>

#define NU 50000
#define NI 50000
#define NN 100000            // NU + NI
#define DD 64
#define EE 1600000
#define E2 3200000           // 2*EE directed edges
#define NB 4096              // batch pairs
#define FULLM 0xffffffffu
#define SCAN_BLKS ((NN + 1023) / 1024)   // 98

#define CNT_BLKS ((EE + 255) / 256)      // 6250
#define FLG_BLKS ((2 * NB + 255) / 256)  // 32
#define FIL_BLKS ((EE + 255) / 256)      // 6250
#define INI_BLKS ((NN * 32 + 255) / 256) // 12500

// ---------------- device scratch (static, no runtime allocation) -----------
__device__ int            g_deg[NN];
__device__ float          g_dinv[NN];
__device__ int            g_rowptr[NN + 1];
__device__ int            g_bsum[SCAN_BLKS];
__device__ unsigned short g_ku[EE];   // occurrence index of edge within user row
__device__ unsigned short g_ki[EE];   // occurrence index of edge within item row
__device__ int            g_col[E2];  // compact CSR adjacency
__device__ unsigned char  g_flag[NN]; // 1 if node appears in users/items sample
// ping-pong fp16 gather buffers holding xs = dinv * x  (row = 128B)
__device__ __half2 g_x[(size_t)NN * 32];
__device__ __half2 g_y[(size_t)NN * 32];
__device__ float   g_acc[(size_t)NN * DD];  // fp32 sum, maintained ONLY at flagged nodes

// ---------------- graph build ----------------------------------------------

// count degrees + record occurrence indices; tail blocks mark sampled nodes
__global__ void k_count(const int* __restrict__ edge,
                        const int* __restrict__ users,
                        const int* __restrict__ items) {
    int b = blockIdx.x;
    if (b < CNT_BLKS) {
        int e = b * 256 + threadIdx.x;
        if (e >= EE) return;
        int u  = edge[e];
        int it = NU + edge[EE + e];
        g_ku[e] = (unsigned short)atomicAdd(&g_deg[u],  1);
        g_ki[e] = (unsigned short)atomicAdd(&g_deg[it], 1);
    } else {
        int i = (b - CNT_BLKS) * 256 + threadIdx.x;
        if (i < NB)           g_flag[users[i]] = 1;
        else if (i < 2 * NB)  g_flag[NU + items[i - NB]] = 1;
    }
}

// phase 1: block-local scan of degrees; also computes dinv (deg already final)
__global__ void k_scan1() {
    __shared__ int wsum[32];
    int idx  = blockIdx.x * 1024 + threadIdx.x;
    int lane = threadIdx.x & 31;
    int wid  = threadIdx.x >> 5;
    int v = (idx < NN) ? g_deg[idx] : 0;
    if (idx < NN) g_dinv[idx] = (v > 0) ? rsqrtf((float)v) : 0.0f;
    int s = v;
    #pragma unroll
    for (int o = 1; o < 32; o <<= 1) {
        int t = __shfl_up_sync(FULLM, s, o);
        if (lane >= o) s += t;
    }
    if (lane == 31) wsum[wid] = s;
    __syncthreads();
    if (wid == 0) {
        int ws = wsum[lane];
        #pragma unroll
        for (int o = 1; o < 32; o <<= 1) {
            int t = __shfl_up_sync(FULLM, ws, o);
            if (lane >= o) ws += t;
        }
        wsum[lane] = ws;
    }
    __syncthreads();
    int off = (wid > 0 ? wsum[wid - 1] : 0);
    if (idx < NN) g_rowptr[idx] = off + s - v;        // block-local exclusive
    if (threadIdx.x == 0) g_bsum[blockIdx.x] = wsum[31];
}

// phase 2+3 fused: warp 0 of each block scans the 98 block sums into smem,
// then all threads add their block offset.
__global__ void k_scan3() {
    __shared__ int sb[SCAN_BLKS];
    int lane = threadIdx.x & 31;
    if (threadIdx.x < 32) {
        int carry = 0;
        #pragma unroll
        for (int base = 0; base < SCAN_BLKS; base += 32) {
            int i2 = base + lane;
            int v = (i2 < SCAN_BLKS) ? g_bsum[i2] : 0;
            int s = v;
            #pragma unroll
            for (int o = 1; o < 32; o <<= 1) {
                int t = __shfl_up_sync(FULLM, s, o);
                if (lane >= o) s += t;
            }
            if (i2 < SCAN_BLKS) sb[i2] = carry + s - v;   // exclusive
            carry += __shfl_sync(FULLM, s, 31);
        }
    }
    __syncthreads();
    int idx = blockIdx.x * blockDim.x + threadIdx.x;
    if (idx >= NN) return;
    g_rowptr[idx] = g_rowptr[idx] + sb[idx >> 10];
    if (idx == 0) g_rowptr[NN] = E2;
}

// fused: blocks [0, FIL_BLKS) fill compact CSR (atomic-free);
// blocks [FIL_BLKS, ...) do initx (x = fp16(dinv*e0); acc = e0 at flagged)
__global__ void k_fillinit(const int* __restrict__ edge,
                           const float* __restrict__ ue,
                           const float* __restrict__ ie) {
    int b = blockIdx.x;
    if (b < FIL_BLKS) {
        int e = b * 256 + threadIdx.x;
        if (e >= EE) return;
        int u  = edge[e];
        int it = NU + edge[EE + e];
        g_col[g_rowptr[u]  + (int)g_ku[e]] = it;
        g_col[g_rowptr[it] + (int)g_ki[e]] = u;
    } else {
        int i = (b - FIL_BLKS) * 256 + threadIdx.x;   // i in [0, NN*32)
        if (i >= NN * 32) return;
        int node = i >> 5;
        int lane = i & 31;
        const float* src = (node < NU) ? (ue + ((size_t)node << 6))
                                       : (ie + ((size_t)(node - NU) << 6));
        float2 v = *((const float2*)src + lane);
        if (g_flag[node])
            *((float2*)(g_acc + ((size_t)node << 6)) + lane) = v;
        float d = g_dinv[node];
        g_x[((size_t)node << 5) + lane] = __floats2half2_rn(d * v.x, d * v.y);
    }
}

// ---------------- propagation ----------------------------------------------

// warp per node, 2 edges per LDG: each half-warp (16 lanes x uint2 = 128B row)
// gathers a different neighbor per load. Col indices fetched 8-wide and
// distributed via shfl.idx. fp16 4-edge trees -> fp32 accum. Halves merged
// via shfl_xor(16). Epilogue: half 1 stores fp16 dst; half 0 updates fp32
// acc only at flagged nodes.
__global__ void k_prop(int flip) {
    const uint2* __restrict__ src = (const uint2*)(flip ? g_y : g_x);
    uint2*       __restrict__ dst = (uint2*)(flip ? g_x : g_y);
    int node = (blockIdx.x * blockDim.x + threadIdx.x) >> 5;
    if (node >= NN) return;
    int lane = threadIdx.x & 31;
    int half = lane >> 4;      // which edge of the pair this lane handles
    int fpos = lane & 15;      // uint2 position within the 128B row
    int beg = g_rowptr[node];
    int end = g_rowptr[node + 1];
    float s0 = 0.f, s1 = 0.f, s2 = 0.f, s3 = 0.f;
    int j = beg;
    for (; j + 8 <= end; j += 8) {
        int c8 = g_col[j + (lane & 7)];          // lanes 0-7 carry cols j..j+7
        int ca = __shfl_sync(FULLM, c8, half);
        int cb = __shfl_sync(FULLM, c8, 2 + half);
        int cc = __shfl_sync(FULLM, c8, 4 + half);
        int cd = __shfl_sync(FULLM, c8, 6 + half);
        uint2 va = src[((size_t)ca << 4) + fpos];
        uint2 vb = src[((size_t)cb << 4) + fpos];
        uint2 vc = src[((size_t)cc << 4) + fpos];
        uint2 vd = src[((size_t)cd << 4) + fpos];
        __half2 ta = __hadd2(__hadd2(*(__half2*)&va.x, *(__half2*)&vb.x),
                             __hadd2(*(__half2*)&vc.x, *(__half2*)&vd.x));
        __half2 tb = __hadd2(__hadd2(*(__half2*)&va.y, *(__half2*)&vb.y),
                             __hadd2(*(__half2*)&vc.y, *(__half2*)&vd.y));
        float2 fa = __half22float2(ta);
        float2 fb = __half22float2(tb);
        s0 += fa.x; s1 += fa.y; s2 += fb.x; s3 += fb.y;
    }
    for (; j + 2 <= end; j += 2) {               // 2-edge tail steps
        int c = g_col[j + half];
        uint2 v = src[((size_t)c << 4) + fpos];
        float2 fa = __half22float2(*(__half2*)&v.x);
        float2 fb = __half22float2(*(__half2*)&v.y);
        s0 += fa.x; s1 += fa.y; s2 += fb.x; s3 += fb.y;
    }
    if (j < end && half == 0) {                  // odd last edge: half 0 only
        int c = g_col[j];
        uint2 v = src[((size_t)c << 4) + fpos];
        float2 fa = __half22float2(*(__half2*)&v.x);
        float2 fb = __half22float2(*(__half2*)&v.y);
        s0 += fa.x; s1 += fa.y; s2 += fb.x; s3 += fb.y;
    }
    // merge the two half-warps' partial sums (both halves end with full sums)
    s0 += __shfl_xor_sync(FULLM, s0, 16);
    s1 += __shfl_xor_sync(FULLM, s1, 16);
    s2 += __shfl_xor_sync(FULLM, s2, 16);
    s3 += __shfl_xor_sync(FULLM, s3, 16);
    float d = g_dinv[node];
    if (half == 0) {
        if (g_flag[node]) {                      // warp-uniform branch
            float4* ap = (float4*)g_acc + ((size_t)node << 4) + fpos;
            float4 a = *ap;
            a.x += d * s0; a.y += d * s1; a.z += d * s2; a.w += d * s3;
            *ap = a;
        }
    } else {
        float dd = d * d;
        __half2 w0 = __floats2half2_rn(dd * s0, dd * s1);
        __half2 w1 = __floats2half2_rn(dd * s2, dd * s3);
        uint2 w;
        w.x = *(unsigned*)&w0;
        w.y = *(unsigned*)&w1;
        dst[((size_t)node << 4) + fpos] = w;
    }
}

// warp per (user,item) pair: out = dot(acc_u, acc_i) / 25
__global__ void k_dot(const int* __restrict__ users, const int* __restrict__ items,
                      float* __restrict__ out) {
    int w = (blockIdx.x * blockDim.x + threadIdx.x) >> 5;
    if (w >= NB) return;
    int lane = threadIdx.x & 31;
    int u  = users[w];
    int it = NU + items[w];
    float2 a = *((const float2*)(g_acc + ((size_t)u  << 6)) + lane);
    float2 b = *((const float2*)(g_acc + ((size_t)it << 6)) + lane);
    float s = a.x * b.x + a.y * b.y;
    #pragma unroll
    for (int o = 16; o; o >>= 1) s += __shfl_down_sync(FULLM, s, o);
    if (lane == 0) out[w] = s * 0.04f;   // (1/5)*(1/5) from the two means
}

// ---------------- host launcher --------------------------------------------

extern "C" void kernel_launch(void* const* d_in, const int* in_sizes, int n_in,
                              void* d_out, int out_size) {
    const float* uemb  = (const float*)d_in[0];
    const float* iemb  = (const float*)d_in[1];
    const int*   edge  = (const int*)d_in[2];
    const int*   users = (const int*)d_in[3];
    const int*   items = (const int*)d_in[4];
    float*       out   = (float*)d_out;

    const int T = 256;
    void* p = nullptr;
    cudaGetSymbolAddress(&p, g_deg);
    cudaMemsetAsync(p, 0, NN * sizeof(int));
    cudaGetSymbolAddress(&p, g_flag);
    cudaMemsetAsync(p, 0, NN);

    k_count   <<<CNT_BLKS + FLG_BLKS, T>>>(edge, users, items);
    k_scan1   <<<SCAN_BLKS, 1024>>>();                 // + dinv
    k_scan3   <<<(NN + T - 1) / T, T>>>();
    k_fillinit<<<FIL_BLKS + INI_BLKS, T>>>(edge, uemb, iemb);

    // 4 propagation layers, ping-pong g_x <-> g_y (selected in-kernel)
    k_prop<<<(NN * 32 + T - 1) / T, T>>>(0);
    k_prop<<<(NN * 32 + T - 1) / T, T>>>(1);
    k_prop<<<(NN * 32 + T - 1) / T, T>>>(0);
    k_prop<<<(NN * 32 + T - 1) / T, T>>>(1);

    k_dot<<<(NB * 32 + T - 1) / T, T>>>(users, items, out);
}